// round 2
// baseline (speedup 1.0000x reference)
#include <cuda_runtime.h>
#include <cuda_bf16.h>

// SoftmaxMarginLoss: ArcFace margin at target logit + scaled softmax CE, mean over batch.
// B=512 rows, C=100000 classes, fp32 logits in (-1,1), labels (int32 OR int64 — sniffed).
//
//   Kernel 1 (hot): streaming sum of exp(64*x - 64) per row-chunk (2048 blocks of 25000
//                   elems). Fixed shift 64 (valid since x<1) -> single pass, no max pass.
//                   exp computed on the FMA pipe (no MUFU) via exp2 magic-round + poly.
//   Kernel 2 (tiny): label-dtype sniff, per-row target-term fixup (margin transform),
//                   logsumexp, NLL, deterministic mean over 512 rows -> d_out[0].

#define NUM_CLASSES 100000
#define BATCH       512
#define CHUNKS      4
#define CHUNK_ELEMS (NUM_CLASSES / CHUNKS)   // 25000, divisible by 4
#define TPB1        256

__device__ float g_partials[BATCH * CHUNKS];

// exp(64*x - 64) for x <= 1, computed entirely on fma/alu pipes (no MUFU).
__device__ __forceinline__ float exp_s64(float x) {
    const float K = 92.33248261689366f;      // 64 * log2(e)
    float u = fmaf(x, K, -K);                // (64x-64)*log2(e), <= 0
    u = fmaxf(u, -125.0f);                   // keep exponent-splice in normal range
    float t = u + 12582912.0f;               // round-to-nearest via magic (2^23 * 1.5)
    float n = t - 12582912.0f;               // n = rint(u)
    float f = u - n;                         // f in [-0.5, 0.5]
    // exp2(f), degree-5 minimax-ish Taylor (rel err ~2.4e-6 on [-0.5,0.5])
    float p = 1.33335581e-3f;
    p = fmaf(p, f, 9.61812911e-3f);
    p = fmaf(p, f, 5.55041087e-2f);
    p = fmaf(p, f, 2.40226507e-1f);
    p = fmaf(p, f, 6.93147181e-1f);
    p = fmaf(p, f, 1.0f);
    int ni = __float_as_int(t) - 0x4B400000; // integer part of u
    return __int_as_float(__float_as_int(p) + (ni << 23));
}

__device__ __forceinline__ float warp_sum(float v) {
    #pragma unroll
    for (int o = 16; o > 0; o >>= 1) v += __shfl_down_sync(0xFFFFFFFFu, v, o);
    return v;
}

__global__ __launch_bounds__(TPB1)
void sumexp_kernel(const float* __restrict__ logits) {
    const int b   = blockIdx.x;           // 0..2047
    const int row = b >> 2;
    const int chk = b & 3;
    const float4* base =
        (const float4*)(logits + (size_t)row * NUM_CLASSES + (size_t)chk * CHUNK_ELEMS);

    float a0 = 0.f, a1 = 0.f, a2 = 0.f, a3 = 0.f;
    const int nvec = CHUNK_ELEMS / 4;     // 6250
    for (int i = threadIdx.x; i < nvec; i += TPB1) {
        float4 v = base[i];
        a0 += exp_s64(v.x);
        a1 += exp_s64(v.y);
        a2 += exp_s64(v.z);
        a3 += exp_s64(v.w);
    }
    float s = (a0 + a1) + (a2 + a3);

    __shared__ float red[TPB1 / 32];
    s = warp_sum(s);
    const int lane = threadIdx.x & 31, wid = threadIdx.x >> 5;
    if (lane == 0) red[wid] = s;
    __syncthreads();
    if (wid == 0) {
        s = (lane < TPB1 / 32) ? red[lane] : 0.f;
        s = warp_sum(s);
        if (lane == 0) g_partials[b] = s;
    }
}

__global__ __launch_bounds__(BATCH)
void finalize_kernel(const float* __restrict__ logits,
                     const void* __restrict__ labels_raw,
                     float* __restrict__ out) {
    const int i = threadIdx.x;            // one thread per row, 512 threads

    // ---- label dtype sniff: int32 vs int64 ----
    // Inspect only the first 512 x 32-bit words (in-bounds for both layouts).
    // int64 layout: words at odd indices are the high halves of values < 1e5 -> all 0.
    // int32 layout: odd words are real labels; all-zero is (1e-5)^256-improbable.
    const int* w = (const int*)labels_raw;
    __shared__ int odd_or;
    if (i == 0) odd_or = 0;
    __syncthreads();
    if (i < 256 && w[2 * i + 1] != 0) atomicOr(&odd_or, 1);
    __syncthreads();
    const bool is_i64 = (odd_or == 0);

    long long L = is_i64 ? ((const long long*)labels_raw)[i] : (long long)w[i];
    if (L < 0) L = 0;
    if (L >= NUM_CLASSES) L = NUM_CLASSES - 1;

    float s = g_partials[4 * i] + g_partials[4 * i + 1] +
              g_partials[4 * i + 2] + g_partials[4 * i + 3];

    const float t = logits[(size_t)i * NUM_CLASSES + (size_t)L];

    const float COSM = 0.87758256189037276f;  // cos(0.5)
    const float SINM = 0.47942553860420301f;  // sin(0.5)
    const float EPS  = 1e-7f;
    float tc = fminf(fmaxf(t, -1.0f + EPS), 1.0f - EPS);
    float tn = tc * COSM - sqrtf(fmaxf(1.0f - tc * tc, 0.0f)) * SINM;

    // swap the target term: remove original, insert margin-transformed
    s = s - exp_s64(t) + exp_s64(tn);

    // logsumexp = 64 + log(s);  nll = logsumexp - 64*tn
    float nll = 64.0f + logf(s) - 64.0f * tn;

    __shared__ float red[BATCH / 32];
    float v = warp_sum(nll);
    const int lane = i & 31, wid = i >> 5;
    if (lane == 0) red[wid] = v;
    __syncthreads();
    if (wid == 0) {
        v = (lane < BATCH / 32) ? red[lane] : 0.f;
        v = warp_sum(v);
        if (lane == 0) out[0] = v * (1.0f / (float)BATCH);
    }
}

extern "C" void kernel_launch(void* const* d_in, const int* in_sizes, int n_in,
                              void* d_out, int out_size) {
    const float* logits = (const float*)d_in[0];
    const void*  labels = (const void*)d_in[1];
    if (n_in >= 2 && in_sizes[1] > in_sizes[0]) {
        // defensive: inputs arrived (labels, logits)
        labels = (const void*)d_in[0];
        logits = (const float*)d_in[1];
    }
    float* out = (float*)d_out;

    sumexp_kernel<<<BATCH * CHUNKS, TPB1>>>(logits);
    finalize_kernel<<<1, BATCH>>>(logits, labels, out);
}

// round 3
// speedup vs baseline: 1.0398x; 1.0398x over previous
#include <cuda_runtime.h>
#include <cuda_bf16.h>

// SoftmaxMarginLoss (ArcFace margin + scaled softmax CE, mean over batch).
// B=512, C=100000, fp32 logits in [-1,1), labels int32-or-int64 (sniffed).
//
// Single fused kernel:
//   2048 blocks each sum 2^96*exp(64x-64) over a 25000-elem row chunk using
//   packed f32x2 FMA (FFMA2) exp2-by-bit-splice (no MUFU, no clamp: the +96
//   exponent re-bias keeps all splices in normal range for x in [-1,1)).
//   Last block (atomic ticket) does the per-row target fixup, logsumexp, NLL,
//   and the deterministic mean -> d_out[0].

#define NUM_CLASSES 100000
#define BATCH       512
#define CHUNKS      4
#define CHUNK_ELEMS (NUM_CLASSES / CHUNKS)   // 25000 (divisible by 4)
#define NVEC        (CHUNK_ELEMS / 4)        // 6250 float4 per block
#define TPB         256
#define GRID        (BATCH * CHUNKS)         // 2048

__device__ float        g_partials[GRID];
__device__ unsigned int g_count;             // zero-init; self-resets each run

// ---- constants for 2^96 * exp(64x - 64) = 2^(x*K + C) ----
#define KF 92.33248261689366f                 /* 64*log2(e) */
#define CF 3.667517383106341f                 /* 96 - 64*log2(e) */
#define MAGICF 12582912.0f                    /* 1.5 * 2^23 */
#define LN2_96 66.54212933375475f             /* 96*ln(2) */

__device__ __forceinline__ unsigned long long pk2(float x) {
    unsigned int b = __float_as_uint(x);
    return ((unsigned long long)b << 32) | (unsigned long long)b;
}

// acc2 += 2^(x*K + C) for both packed halves. All heavy math on FFMA2.
__device__ __forceinline__ void exp2pair_acc(
    unsigned long long x2, unsigned long long& acc2,
    unsigned long long K2, unsigned long long C2,
    unsigned long long M2, unsigned long long nM2, unsigned long long NEG1,
    unsigned long long P3, unsigned long long P2, unsigned long long P1,
    unsigned long long P0)
{
    unsigned long long u2, t2, n2, f2, p2, e2;
    asm("fma.rn.f32x2 %0, %1, %2, %3;" : "=l"(u2) : "l"(x2), "l"(K2), "l"(C2));
    asm("add.rn.f32x2 %0, %1, %2;"     : "=l"(t2) : "l"(u2), "l"(M2));   // rne(u)+MAGIC
    asm("add.rn.f32x2 %0, %1, %2;"     : "=l"(n2) : "l"(t2), "l"(nM2));  // n = rne(u)
    asm("fma.rn.f32x2 %0, %1, %2, %3;" : "=l"(f2) : "l"(n2), "l"(NEG1), "l"(u2)); // f=u-n
    asm("fma.rn.f32x2 %0, %1, %2, %3;" : "=l"(p2) : "l"(P3), "l"(f2), "l"(P2));
    asm("fma.rn.f32x2 %0, %1, %2, %3;" : "=l"(p2) : "l"(p2), "l"(f2), "l"(P1));
    asm("fma.rn.f32x2 %0, %1, %2, %3;" : "=l"(p2) : "l"(p2), "l"(f2), "l"(P0));
    // exponent splice: bits(t) = 0x4B400000 + n, and 0x4B400000<<23 == 0 mod 2^32,
    // so e_bits = p_bits + (t_bits << 23) gives p * 2^n exactly.
    unsigned int tlo, thi, plo, phi;
    asm("mov.b64 {%0,%1}, %2;" : "=r"(tlo), "=r"(thi) : "l"(t2));
    asm("mov.b64 {%0,%1}, %2;" : "=r"(plo), "=r"(phi) : "l"(p2));
    unsigned int elo = plo + (tlo << 23);
    unsigned int ehi = phi + (thi << 23);
    asm("mov.b64 %0, {%1,%2};" : "=l"(e2) : "r"(elo), "r"(ehi));
    asm("add.rn.f32x2 %0, %1, %2;" : "=l"(acc2) : "l"(acc2), "l"(e2));
}

__device__ __forceinline__ float warp_sum(float v) {
    #pragma unroll
    for (int o = 16; o > 0; o >>= 1) v += __shfl_down_sync(0xFFFFFFFFu, v, o);
    return v;
}

// precise scalar 2^96*exp(64y-64) for the finalize fixup (MUFU is fine here)
__device__ __forceinline__ float exp_s64_scaled(float y) {
    return exp2f(fmaf(y, KF, CF));
}

__global__ __launch_bounds__(TPB)
void fused_kernel(const float* __restrict__ logits,
                  const void*  __restrict__ labels_raw,
                  float*       __restrict__ out)
{
    const int b   = blockIdx.x;
    const int row = b >> 2;
    const int chk = b & 3;
    const float4* base =
        (const float4*)(logits + (size_t)row * NUM_CLASSES + (size_t)chk * CHUNK_ELEMS);

    const unsigned long long K2   = pk2(KF);
    const unsigned long long C2   = pk2(CF);
    const unsigned long long M2   = pk2(MAGICF);
    const unsigned long long nM2  = pk2(-MAGICF);
    const unsigned long long NEG1 = pk2(-1.0f);
    const unsigned long long P3   = pk2(0.05550410866482158f);
    const unsigned long long P2   = pk2(0.2402265069591007f);
    const unsigned long long P1   = pk2(0.6931471805599453f);
    const unsigned long long P0   = pk2(1.0f);

    unsigned long long accA = 0ull, accB = 0ull;   // packed {0,0}
    #pragma unroll 2
    for (int i = threadIdx.x; i < NVEC; i += TPB) {
        float4 v = __ldcs(base + i);
        unsigned long long xa, xb;
        asm("mov.b64 %0, {%1,%2};" : "=l"(xa) : "f"(v.x), "f"(v.y));
        asm("mov.b64 %0, {%1,%2};" : "=l"(xb) : "f"(v.z), "f"(v.w));
        exp2pair_acc(xa, accA, K2, C2, M2, nM2, NEG1, P3, P2, P1, P0);
        exp2pair_acc(xb, accB, K2, C2, M2, nM2, NEG1, P3, P2, P1, P0);
    }
    float a0, a1, a2, a3;
    asm("mov.b64 {%0,%1}, %2;" : "=f"(a0), "=f"(a1) : "l"(accA));
    asm("mov.b64 {%0,%1}, %2;" : "=f"(a2), "=f"(a3) : "l"(accB));
    float s = (a0 + a1) + (a2 + a3);

    __shared__ float red[TPB / 32];
    __shared__ unsigned int ticket;
    __shared__ int odd_or;
    s = warp_sum(s);
    const int lane = threadIdx.x & 31, wid = threadIdx.x >> 5;
    if (lane == 0) red[wid] = s;
    __syncthreads();
    if (threadIdx.x == 0) {
        float t = 0.f;
        #pragma unroll
        for (int k = 0; k < TPB / 32; k++) t += red[k];
        g_partials[b] = t;
        __threadfence();
        ticket = atomicAdd(&g_count, 1u);
        odd_or = 0;
    }
    __syncthreads();
    if (ticket != GRID - 1) return;

    // ================= last block: finalize =================
    const int i = threadIdx.x;

    // label dtype sniff (first 512 x 32-bit words are in-bounds for both layouts)
    const int* w = (const int*)labels_raw;
    if (w[2 * i + 1] != 0) atomicOr(&odd_or, 1);
    __syncthreads();
    const bool is_i64 = (odd_or == 0);

    const float COSM = 0.87758256189037276f;  // cos(0.5)
    const float SINM = 0.47942553860420301f;  // sin(0.5)
    const float EPS  = 1e-7f;

    float vsum = 0.f;
    #pragma unroll
    for (int rr = 0; rr < BATCH / TPB; rr++) {
        const int r = i + rr * TPB;
        long long L = is_i64 ? ((const long long*)labels_raw)[r] : (long long)w[r];
        if (L < 0) L = 0;
        if (L >= NUM_CLASSES) L = NUM_CLASSES - 1;

        float S = (g_partials[4 * r] + g_partials[4 * r + 1]) +
                  (g_partials[4 * r + 2] + g_partials[4 * r + 3]);

        const float t = logits[(size_t)r * NUM_CLASSES + (size_t)L];
        float tc = fminf(fmaxf(t, -1.0f + EPS), 1.0f - EPS);
        float tn = tc * COSM - sqrtf(fmaxf(1.0f - tc * tc, 0.0f)) * SINM;

        S = S - exp_s64_scaled(t) + exp_s64_scaled(tn);
        // nll = (64 + log(S) - 96*ln2) - 64*tn
        vsum += 64.0f + logf(S) - LN2_96 - 64.0f * tn;
    }

    float v = warp_sum(vsum);
    if (lane == 0) red[wid] = v;
    __syncthreads();
    if (wid == 0) {
        v = (lane < TPB / 32) ? red[lane] : 0.f;
        v = warp_sum(v);
        if (lane == 0) {
            out[0] = v * (1.0f / (float)BATCH);
            g_count = 0;   // reset for next graph replay
        }
    }
}

extern "C" void kernel_launch(void* const* d_in, const int* in_sizes, int n_in,
                              void* d_out, int out_size) {
    const float* logits = (const float*)d_in[0];
    const void*  labels = (const void*)d_in[1];
    if (n_in >= 2 && in_sizes[1] > in_sizes[0]) {   // defensive swap
        labels = (const void*)d_in[0];
        logits = (const float*)d_in[1];
    }
    fused_kernel<<<GRID, TPB>>>(logits, labels, (float*)d_out);
}